// round 14
// baseline (speedup 1.0000x reference)
#include <cuda_runtime.h>
#include <cuda_fp16.h>
#include <cstdint>

#define TOKENS 32768
#define DIN    1024
#define DOUT   1024
#define RANK   16

// ---------------- global scratch ----------------
__device__ __half g_whi[DOUT * DIN];             // 2 MB folded fp16 weight

// ---------------- fold W + LoRA, convert to fp16 ----------------
__global__ __launch_bounds__(256)
void build_w_kernel(const float* __restrict__ W,
                    const float* __restrict__ A1, const float* __restrict__ B1,
                    const float* __restrict__ A2, const float* __restrict__ B2) {
    int idx = blockIdx.x * 256 + threadIdx.x;   // 0 .. DOUT*DIN-1
    int o = idx >> 10;
    int i = idx & 1023;
    float s1 = 0.f, s2 = 0.f;
#pragma unroll
    for (int r = 0; r < RANK; ++r) {
        s1 = fmaf(B1[o * RANK + r], A1[r * DIN + i], s1);
        s2 = fmaf(B2[o * RANK + r], A2[r * DIN + i], s2);
    }
    float w = W[idx] + 0.5f * s1 + s2;          // SCALE1=8/16, SCALE2=16/16
    g_whi[idx] = __float2half_rn(w);
}

// ---------------- fused GEMM: out = fp16(x) @ whi^T + b ----------------
// R8 shape (128x128 tile, 8 warps, 4x16KB stages, 2 CTAs/SM) with x
// converted fp32->fp16 in-register, split into two 8-float chunks per
// stage to cap live registers (occ-2 is the latency-hiding floor).
#define BK      32
#define STAGES  4
#define XO      0                  // x tile: 128 x 32 fp16 = 8 KB
#define WO      8192               // w tile: 128 x 32 fp16 = 8 KB
#define STG     16384
#define NKT     (DIN / BK)         // 32

__device__ __forceinline__ uint32_t smem_u32(const void* p) {
    uint32_t a;
    asm("{ .reg .u64 t; cvta.to.shared.u64 t, %1; cvt.u32.u64 %0, t; }" : "=r"(a) : "l"(p));
    return a;
}
__device__ __forceinline__ uint32_t swz64(uint32_t o) { return o ^ ((o >> 3) & 0x30); }

__device__ __forceinline__ void ldsm4(uint32_t* r, uint32_t addr) {
    asm volatile("ldmatrix.sync.aligned.m8n8.x4.shared.b16 {%0,%1,%2,%3}, [%4];"
        : "=r"(r[0]), "=r"(r[1]), "=r"(r[2]), "=r"(r[3]) : "r"(addr));
}
__device__ __forceinline__ void mma16816(float* c, const uint32_t* a, const uint32_t* b) {
    asm volatile("mma.sync.aligned.m16n8k16.row.col.f32.f16.f16.f32 "
        "{%0,%1,%2,%3}, {%4,%5,%6,%7}, {%8,%9}, {%0,%1,%2,%3};"
        : "+f"(c[0]), "+f"(c[1]), "+f"(c[2]), "+f"(c[3])
        : "r"(a[0]), "r"(a[1]), "r"(a[2]), "r"(a[3]), "r"(b[0]), "r"(b[1]));
}

#define CP16(dst, src) \
    asm volatile("cp.async.cg.shared.global [%0], [%1], 16;" :: "r"(dst), "l"(src))
#define CP_COMMIT() asm volatile("cp.async.commit_group;")
#define CP_WAIT2()  asm volatile("cp.async.wait_group 2;")

__global__ void __launch_bounds__(256, 2)
gemm_fused(const float* __restrict__ X, const float* __restrict__ bias,
           float* __restrict__ out) {
    extern __shared__ char sm[];
    const uint32_t sb = smem_u32(sm);
    const int tid  = threadIdx.x;
    const int lane = tid & 31;
    const int wid  = tid >> 5;
    const int wm   = wid & 3;        // 4 m-groups of 32
    const int wn   = wid >> 2;       // 2 n-groups of 64
    const int m0   = blockIdx.y * 128;
    const int n0   = blockIdx.x * 128;

    // W cp.async mapping: rows tid/4 and +64, 16B chunk col = tid%4
    const int crow = tid >> 2;
    const int ccol = tid & 3;
    const __half* gwh = g_whi + (size_t)(n0 + crow) * DIN + ccol * 8;
    const uint32_t wsts = swz64((uint32_t)crow * 64 + (uint32_t)ccol * 16);

    // x fp32 LDG mapping: row tid/2, k-half tid%2 -> 16 floats, two 8-float chunks
    const int xrow = tid >> 1;
    const int xkh  = tid & 1;
    const float* xg = X + (size_t)(m0 + xrow) * DIN + xkh * 16;
    const uint32_t xsts0 = swz64((uint32_t)xrow * 64 + (uint32_t)xkh * 32);
    const uint32_t xsts1 = swz64((uint32_t)xrow * 64 + (uint32_t)xkh * 32 + 16);

    // unswizzled ldmatrix lane offsets; swizzle applied after adding ks
    const uint32_t a_off = (uint32_t)(wm * 32 + (lane & 15)) * 64 + (uint32_t)(lane >> 4) * 16;
    const uint32_t b_off = (uint32_t)(wn * 64 + (lane >> 4) * 8 + (lane & 7)) * 64 +
                           (uint32_t)((lane >> 3) & 1) * 16;

    float acc[2][8][4];
#pragma unroll
    for (int mt = 0; mt < 2; ++mt)
#pragma unroll
        for (int nt = 0; nt < 8; ++nt)
#pragma unroll
            for (int c = 0; c < 4; ++c) acc[mt][nt][c] = 0.f;

#define ISSUE_W(kt) do {                                                           \
        const uint32_t st_ = sb + WO + ((kt) % STAGES) * STG;                      \
        const size_t go_ = (size_t)(kt) * BK;                                      \
        CP16(st_ + wsts,        gwh + go_);                                       \
        CP16(st_ + wsts + 4096, gwh + go_ + (size_t)64 * DIN);                    \
    } while (0)

    // convert 8 fp32 -> 8 fp16 (16B) and STS at given swizzled slot offset
#define XCVT8_STS(kt, f0, f1, xsts) do {                                           \
        const uint32_t st_ = sb + XO + ((kt) % STAGES) * STG;                      \
        union { __half2 h2[4]; uint4 q; } U;                                       \
        U.h2[0] = __floats2half2_rn((f0).x, (f0).y);                               \
        U.h2[1] = __floats2half2_rn((f0).z, (f0).w);                               \
        U.h2[2] = __floats2half2_rn((f1).x, (f1).y);                               \
        U.h2[3] = __floats2half2_rn((f1).z, (f1).w);                               \
        asm volatile("st.shared.v4.b32 [%0], {%1,%2,%3,%4};" :: "r"(st_ + (xsts)),\
            "r"(U.q.x), "r"(U.q.y), "r"(U.q.z), "r"(U.q.w));                       \
    } while (0)

    // prologue: stages 0-2 (W async + x sync)
#pragma unroll
    for (int p = 0; p < 3; ++p) {
        ISSUE_W(p); CP_COMMIT();
        const float4* xp = reinterpret_cast<const float4*>(xg + p * BK);
        float4 f0 = xp[0], f1 = xp[1];
        XCVT8_STS(p, f0, f1, xsts0);
        f0 = xp[2]; f1 = xp[3];
        XCVT8_STS(p, f0, f1, xsts1);
    }

#pragma unroll 1
    for (int kt = 0; kt < NKT; ++kt) {
        CP_WAIT2();
        __syncthreads();

        const bool pf = (kt + 3 < NKT);
        const float4* xp = reinterpret_cast<const float4*>(xg + (kt + 3) * BK);
        float4 xc0, xc1;
        if (pf) {
            xc0 = xp[0]; xc1 = xp[1];      // chunk 0 LDG (hidden under s-step 0)
            ISSUE_W(kt + 3);
        }
        CP_COMMIT();

        const uint32_t stx = sb + XO + (kt % STAGES) * STG;
        const uint32_t stw = sb + WO + (kt % STAGES) * STG;

        // ---- s-step 0 ----
        {
            const uint32_t a_sw = swz64(a_off);
            const uint32_t b_sw = swz64(b_off);
            uint32_t bh[4][4];
#pragma unroll
            for (int j = 0; j < 4; ++j) ldsm4(bh[j], stw + b_sw + j * 1024);
            uint32_t ah[2][4];
#pragma unroll
            for (int mt = 0; mt < 2; ++mt) ldsm4(ah[mt], stx + a_sw + mt * 1024);
#pragma unroll
            for (int mt = 0; mt < 2; ++mt)
#pragma unroll
                for (int nt = 0; nt < 8; ++nt)
                    mma16816(acc[mt][nt], ah[mt], &bh[nt >> 1][(nt & 1) * 2]);
        }

        if (pf) {
            XCVT8_STS(kt + 3, xc0, xc1, xsts0);   // chunk 0 done; free its regs
            xc0 = xp[2]; xc1 = xp[3];             // chunk 1 LDG (hidden under s-step 1)
        }

        // ---- s-step 1 ----
        {
            const uint32_t a_sw = swz64(a_off + 32);
            const uint32_t b_sw = swz64(b_off + 32);
            uint32_t bh[4][4];
#pragma unroll
            for (int j = 0; j < 4; ++j) ldsm4(bh[j], stw + b_sw + j * 1024);
            uint32_t ah[2][4];
#pragma unroll
            for (int mt = 0; mt < 2; ++mt) ldsm4(ah[mt], stx + a_sw + mt * 1024);
#pragma unroll
            for (int mt = 0; mt < 2; ++mt)
#pragma unroll
                for (int nt = 0; nt < 8; ++nt)
                    mma16816(acc[mt][nt], ah[mt], &bh[nt >> 1][(nt & 1) * 2]);
        }

        if (pf) XCVT8_STS(kt + 3, xc0, xc1, xsts1);
    }

    // ---- epilogue: add bias, store fp32 (float2) ----
    const int erow = m0 + wm * 32 + (lane >> 2);
    const int ecol = n0 + wn * 64 + (lane & 3) * 2;
#pragma unroll
    for (int nt = 0; nt < 8; ++nt) {
        const int c = ecol + nt * 8;
        const float b0 = bias[c], b1 = bias[c + 1];
#pragma unroll
        for (int mt = 0; mt < 2; ++mt) {
            const int r = erow + mt * 16;
            float2 o0 = make_float2(acc[mt][nt][0] + b0, acc[mt][nt][1] + b1);
            float2 o1 = make_float2(acc[mt][nt][2] + b0, acc[mt][nt][3] + b1);
            *reinterpret_cast<float2*>(out + (size_t)r * DOUT + c)       = o0;
            *reinterpret_cast<float2*>(out + (size_t)(r + 8) * DOUT + c) = o1;
        }
    }
}

// ---------------- launch ----------------
extern "C" void kernel_launch(void* const* d_in, const int* in_sizes, int n_in,
                              void* d_out, int out_size) {
    const float* x  = (const float*)d_in[0];
    const float* W  = (const float*)d_in[1];
    const float* b  = (const float*)d_in[2];
    const float* A1 = (const float*)d_in[3];
    const float* B1 = (const float*)d_in[4];
    const float* A2 = (const float*)d_in[5];
    const float* B2 = (const float*)d_in[6];
    float* out = (float*)d_out;

    cudaFuncSetAttribute(gemm_fused, cudaFuncAttributeMaxDynamicSharedMemorySize,
                         STAGES * STG);

    build_w_kernel<<<(DOUT * DIN) / 256, 256>>>(W, A1, B1, A2, B2);

    dim3 grid(DOUT / 128, TOKENS / 128);   // (n-tiles=8, m-tiles=256)
    gemm_fused<<<grid, 256, STAGES * STG>>>(x, b, out);
}

// round 16
// speedup vs baseline: 1.1134x; 1.1134x over previous
#include <cuda_runtime.h>
#include <cuda_fp16.h>
#include <cstdint>

#define TOKENS 32768
#define DIN    1024
#define DOUT   1024
#define RANK   16

// ---------------- global scratch (device statics; no cudaMalloc) ----------------
__device__ __half g_xhi[(size_t)TOKENS * DIN];   // 64 MB
__device__ __half g_whi[DOUT * DIN];             // 2 MB

// ---------------- fold W + LoRA, convert to fp16 ----------------
__global__ __launch_bounds__(256)
void build_w_kernel(const float* __restrict__ W,
                    const float* __restrict__ A1, const float* __restrict__ B1,
                    const float* __restrict__ A2, const float* __restrict__ B2) {
    int idx = blockIdx.x * 256 + threadIdx.x;   // 0 .. DOUT*DIN-1
    int o = idx >> 10;
    int i = idx & 1023;
    float s1 = 0.f, s2 = 0.f;
#pragma unroll
    for (int r = 0; r < RANK; ++r) {
        s1 = fmaf(B1[o * RANK + r], A1[r * DIN + i], s1);
        s2 = fmaf(B2[o * RANK + r], A2[r * DIN + i], s2);
    }
    float w = W[idx] + 0.5f * s1 + s2;          // SCALE1=8/16, SCALE2=16/16
    g_whi[idx] = __float2half_rn(w);
}

// ---------------- convert x to fp16 (16 elems/thread, MLP 4) ----------------
__global__ __launch_bounds__(256)
void split_x_kernel(const float* __restrict__ X) {
    size_t base = ((size_t)blockIdx.x * 256 + threadIdx.x) * 16;
    const float4* xp = reinterpret_cast<const float4*>(X + base);
    float4 f0 = xp[0], f1 = xp[1], f2 = xp[2], f3 = xp[3];
    union { __half2 h2[8]; uint4 q[2]; } U;
    U.h2[0] = __floats2half2_rn(f0.x, f0.y);
    U.h2[1] = __floats2half2_rn(f0.z, f0.w);
    U.h2[2] = __floats2half2_rn(f1.x, f1.y);
    U.h2[3] = __floats2half2_rn(f1.z, f1.w);
    U.h2[4] = __floats2half2_rn(f2.x, f2.y);
    U.h2[5] = __floats2half2_rn(f2.z, f2.w);
    U.h2[6] = __floats2half2_rn(f3.x, f3.y);
    U.h2[7] = __floats2half2_rn(f3.z, f3.w);
    uint4* op = reinterpret_cast<uint4*>(g_xhi + base);
    op[0] = U.q[0];
    op[1] = U.q[1];
}

// ---------------- GEMM: out = xhi @ whi^T + b, single-pass fp16 HMMA ----------------
// 128x128 CTA tile, 8 warps (4m x 2n of 32x64), BK=64, 3 stages x 32KB.
#define BK      64
#define STAGES  3
#define XO      0                  // x tile: 128 x 64 fp16 = 16 KB
#define WO      16384              // w tile: 128 x 64 fp16 = 16 KB
#define STG     32768
#define NKT     (DIN / BK)         // 16

__device__ __forceinline__ uint32_t smem_u32(const void* p) {
    uint32_t a;
    asm("{ .reg .u64 t; cvta.to.shared.u64 t, %1; cvt.u32.u64 %0, t; }" : "=r"(a) : "l"(p));
    return a;
}
// SW128 swizzle: 128B rows, XOR bits[6:4] ^= bits[9:7]
__device__ __forceinline__ uint32_t swz128(uint32_t o) { return o ^ ((o >> 3) & 0x70); }

__device__ __forceinline__ void ldsm4(uint32_t* r, uint32_t addr) {
    asm volatile("ldmatrix.sync.aligned.m8n8.x4.shared.b16 {%0,%1,%2,%3}, [%4];"
        : "=r"(r[0]), "=r"(r[1]), "=r"(r[2]), "=r"(r[3]) : "r"(addr));
}
__device__ __forceinline__ void mma16816(float* c, const uint32_t* a, const uint32_t* b) {
    asm volatile("mma.sync.aligned.m16n8k16.row.col.f32.f16.f16.f32 "
        "{%0,%1,%2,%3}, {%4,%5,%6,%7}, {%8,%9}, {%0,%1,%2,%3};"
        : "+f"(c[0]), "+f"(c[1]), "+f"(c[2]), "+f"(c[3])
        : "r"(a[0]), "r"(a[1]), "r"(a[2]), "r"(a[3]), "r"(b[0]), "r"(b[1]));
}

#define CP16(dst, src) \
    asm volatile("cp.async.cg.shared.global [%0], [%1], 16;" :: "r"(dst), "l"(src))
#define CP_COMMIT() asm volatile("cp.async.commit_group;")
#define CP_WAIT1()  asm volatile("cp.async.wait_group 1;")

__global__ void __launch_bounds__(256, 2)
gemm_fp16(const float* __restrict__ bias, float* __restrict__ out) {
    extern __shared__ char sm[];
    const uint32_t sb = smem_u32(sm);
    const int tid  = threadIdx.x;
    const int lane = tid & 31;
    const int wid  = tid >> 5;
    const int wm   = wid & 3;        // 4 m-groups of 32
    const int wn   = wid >> 2;       // 2 n-groups of 64
    const int m0   = blockIdx.y * 128;
    const int n0   = blockIdx.x * 128;

    // cp.async mapping: 2 threads per 128B row; each thread 4 x 16B chunks
    const int crow = tid >> 1;       // 0..127
    const int ccol = tid & 1;        // 0/1 (row half: 64B)
    const __half* gxh = g_xhi + (size_t)(m0 + crow) * DIN + ccol * 32;
    const __half* gwh = g_whi + (size_t)(n0 + crow) * DIN + ccol * 32;
    uint32_t stsj[4];
#pragma unroll
    for (int j = 0; j < 4; ++j)
        stsj[j] = swz128((uint32_t)crow * 128 + (uint32_t)ccol * 64 + j * 16);

    // unswizzled ldmatrix lane offsets; k-offset (ks) added pre-swizzle
    const uint32_t a_off = (uint32_t)(wm * 32 + (lane & 15)) * 128 + (uint32_t)(lane >> 4) * 16;
    const uint32_t b_off = (uint32_t)(wn * 64 + (lane >> 4) * 8 + (lane & 7)) * 128 +
                           (uint32_t)((lane >> 3) & 1) * 16;

    float acc[2][8][4];
#pragma unroll
    for (int mt = 0; mt < 2; ++mt)
#pragma unroll
        for (int nt = 0; nt < 8; ++nt)
#pragma unroll
            for (int c = 0; c < 4; ++c) acc[mt][nt][c] = 0.f;

#define ISSUE(kt) do {                                                            \
        const uint32_t st_ = sb + ((kt) % STAGES) * STG;                          \
        const size_t go_ = (size_t)(kt) * BK;                                     \
        CP16(st_ + XO + stsj[0], gxh + go_);                                      \
        CP16(st_ + XO + stsj[1], gxh + go_ + 8);                                  \
        CP16(st_ + XO + stsj[2], gxh + go_ + 16);                                 \
        CP16(st_ + XO + stsj[3], gxh + go_ + 24);                                 \
        CP16(st_ + WO + stsj[0], gwh + go_);                                      \
        CP16(st_ + WO + stsj[1], gwh + go_ + 8);                                  \
        CP16(st_ + WO + stsj[2], gwh + go_ + 16);                                 \
        CP16(st_ + WO + stsj[3], gwh + go_ + 24);                                 \
    } while (0)

    ISSUE(0); CP_COMMIT();
    ISSUE(1); CP_COMMIT();

#pragma unroll 1
    for (int kt = 0; kt < NKT; ++kt) {
        CP_WAIT1();
        __syncthreads();

        if (kt + 2 < NKT) { ISSUE(kt + 2); }
        CP_COMMIT();

        const uint32_t stx = sb + XO + (kt % STAGES) * STG;
        const uint32_t stw = sb + WO + (kt % STAGES) * STG;
#pragma unroll
        for (int s = 0; s < 4; ++s) {
            const uint32_t ks = s * 32;                 // 16 fp16 columns per step
            const uint32_t a_sw = swz128(a_off + ks);
            const uint32_t b_sw = swz128(b_off + ks);

            uint32_t bh[4][4];
#pragma unroll
            for (int j = 0; j < 4; ++j)
                ldsm4(bh[j], stw + b_sw + j * 2048);    // +16 n-rows (bit 11, swizzle-safe)

            uint32_t ah[2][4];
#pragma unroll
            for (int mt = 0; mt < 2; ++mt)
                ldsm4(ah[mt], stx + a_sw + mt * 2048);  // +16 m-rows

#pragma unroll
            for (int mt = 0; mt < 2; ++mt)
#pragma unroll
                for (int nt = 0; nt < 8; ++nt)
                    mma16816(acc[mt][nt], ah[mt], &bh[nt >> 1][(nt & 1) * 2]);
        }
    }

    // ---- epilogue: add bias, store fp32 (float2) ----
    const int erow = m0 + wm * 32 + (lane >> 2);
    const int ecol = n0 + wn * 64 + (lane & 3) * 2;
#pragma unroll
    for (int nt = 0; nt < 8; ++nt) {
        const int c = ecol + nt * 8;
        const float b0 = bias[c], b1 = bias[c + 1];
#pragma unroll
        for (int mt = 0; mt < 2; ++mt) {
            const int r = erow + mt * 16;
            float2 o0 = make_float2(acc[mt][nt][0] + b0, acc[mt][nt][1] + b1);
            float2 o1 = make_float2(acc[mt][nt][2] + b0, acc[mt][nt][3] + b1);
            *reinterpret_cast<float2*>(out + (size_t)r * DOUT + c)       = o0;
            *reinterpret_cast<float2*>(out + (size_t)(r + 8) * DOUT + c) = o1;
        }
    }
}

// ---------------- launch ----------------
extern "C" void kernel_launch(void* const* d_in, const int* in_sizes, int n_in,
                              void* d_out, int out_size) {
    const float* x  = (const float*)d_in[0];
    const float* W  = (const float*)d_in[1];
    const float* b  = (const float*)d_in[2];
    const float* A1 = (const float*)d_in[3];
    const float* B1 = (const float*)d_in[4];
    const float* A2 = (const float*)d_in[5];
    const float* B2 = (const float*)d_in[6];
    float* out = (float*)d_out;

    cudaFuncSetAttribute(gemm_fp16, cudaFuncAttributeMaxDynamicSharedMemorySize,
                         STAGES * STG);

    build_w_kernel<<<(DOUT * DIN) / 256, 256>>>(W, A1, B1, A2, B2);
    split_x_kernel<<<(int)(((size_t)TOKENS * DIN) / 16 / 256), 256>>>(x);

    dim3 grid(DOUT / 128, TOKENS / 128);   // (n-tiles=8, m-tiles=256)
    gemm_fp16<<<grid, 256, STAGES * STG>>>(b, out);
}

// round 17
// speedup vs baseline: 1.4062x; 1.2630x over previous
#include <cuda_runtime.h>
#include <cuda_fp16.h>
#include <cstdint>

#define TOKENS 32768
#define DIN    1024
#define DOUT   1024
#define RANK   16

// ---------------- global scratch (device statics; no cudaMalloc) ----------------
__device__ __half g_xhi[(size_t)TOKENS * DIN];   // 64 MB
__device__ __half g_whi[DOUT * DIN];             // 2 MB

// ---------------- fused prep: split_x blocks + build_w blocks ----------------
// blocks [0, XBLK):      convert x fp32 -> fp16, 16 elems/thread (MLP 4)
// blocks [XBLK, XBLK+WBLK): fold W + LoRA -> fp16, one block per output row
#define XBLK 8192                  // 33.55M elems / 16 / 256
#define WBLK 1024                  // one block per o-row (1024 elems, 4/thread)

__global__ __launch_bounds__(256)
void prep_kernel(const float* __restrict__ X,  const float* __restrict__ W,
                 const float* __restrict__ A1, const float* __restrict__ B1,
                 const float* __restrict__ A2, const float* __restrict__ B2) {
    const int blk = blockIdx.x;
    const int tid = threadIdx.x;

    if (blk < XBLK) {
        // ---- x conversion ----
        size_t base = ((size_t)blk * 256 + tid) * 16;
        const float4* xp = reinterpret_cast<const float4*>(X + base);
        float4 f0 = xp[0], f1 = xp[1], f2 = xp[2], f3 = xp[3];
        union { __half2 h2[8]; uint4 q[2]; } U;
        U.h2[0] = __floats2half2_rn(f0.x, f0.y);
        U.h2[1] = __floats2half2_rn(f0.z, f0.w);
        U.h2[2] = __floats2half2_rn(f1.x, f1.y);
        U.h2[3] = __floats2half2_rn(f1.z, f1.w);
        U.h2[4] = __floats2half2_rn(f2.x, f2.y);
        U.h2[5] = __floats2half2_rn(f2.z, f2.w);
        U.h2[6] = __floats2half2_rn(f3.x, f3.y);
        U.h2[7] = __floats2half2_rn(f3.z, f3.w);
        uint4* op = reinterpret_cast<uint4*>(g_xhi + base);
        op[0] = U.q[0];
        op[1] = U.q[1];
    } else {
        // ---- W fold: o = row, 4 consecutive i per thread ----
        const int o  = blk - XBLK;
        const int i4 = tid * 4;
        float4 wv = *reinterpret_cast<const float4*>(W + (size_t)o * DIN + i4);
        float s1x = 0.f, s1y = 0.f, s1z = 0.f, s1w = 0.f;
        float s2x = 0.f, s2y = 0.f, s2z = 0.f, s2w = 0.f;
#pragma unroll
        for (int r = 0; r < RANK; ++r) {
            const float b1 = B1[o * RANK + r];        // block-uniform -> broadcast
            const float b2 = B2[o * RANK + r];
            float4 a1 = *reinterpret_cast<const float4*>(A1 + (size_t)r * DIN + i4);
            float4 a2 = *reinterpret_cast<const float4*>(A2 + (size_t)r * DIN + i4);
            s1x = fmaf(b1, a1.x, s1x); s1y = fmaf(b1, a1.y, s1y);
            s1z = fmaf(b1, a1.z, s1z); s1w = fmaf(b1, a1.w, s1w);
            s2x = fmaf(b2, a2.x, s2x); s2y = fmaf(b2, a2.y, s2y);
            s2z = fmaf(b2, a2.z, s2z); s2w = fmaf(b2, a2.w, s2w);
        }
        // SCALE1 = 8/16 = 0.5, SCALE2 = 16/16 = 1
        float w0 = wv.x + 0.5f * s1x + s2x;
        float w1 = wv.y + 0.5f * s1y + s2y;
        float w2 = wv.z + 0.5f * s1z + s2z;
        float w3 = wv.w + 0.5f * s1w + s2w;
        union { __half2 h2[2]; uint2 q; } V;
        V.h2[0] = __floats2half2_rn(w0, w1);
        V.h2[1] = __floats2half2_rn(w2, w3);
        *reinterpret_cast<uint2*>(g_whi + (size_t)o * DIN + i4) = V.q;
    }
}

// ---------------- GEMM: out = xhi @ whi^T + b, single-pass fp16 HMMA ----------------
// (byte-identical to the R8 winner: 128x128 tile, 8 warps, BK=32, 4x16KB stages)
#define BK      32
#define STAGES  4
#define XHI_OFF 0
#define WHI_OFF 8192
#define STG     16384
#define NKT     (DIN / BK)         // 32

__device__ __forceinline__ uint32_t smem_u32(const void* p) {
    uint32_t a;
    asm("{ .reg .u64 t; cvta.to.shared.u64 t, %1; cvt.u32.u64 %0, t; }" : "=r"(a) : "l"(p));
    return a;
}
__device__ __forceinline__ uint32_t swz64(uint32_t o) { return o ^ ((o >> 3) & 0x30); }

__device__ __forceinline__ void ldsm4(uint32_t* r, uint32_t addr) {
    asm volatile("ldmatrix.sync.aligned.m8n8.x4.shared.b16 {%0,%1,%2,%3}, [%4];"
        : "=r"(r[0]), "=r"(r[1]), "=r"(r[2]), "=r"(r[3]) : "r"(addr));
}
__device__ __forceinline__ void mma16816(float* c, const uint32_t* a, const uint32_t* b) {
    asm volatile("mma.sync.aligned.m16n8k16.row.col.f32.f16.f16.f32 "
        "{%0,%1,%2,%3}, {%4,%5,%6,%7}, {%8,%9}, {%0,%1,%2,%3};"
        : "+f"(c[0]), "+f"(c[1]), "+f"(c[2]), "+f"(c[3])
        : "r"(a[0]), "r"(a[1]), "r"(a[2]), "r"(a[3]), "r"(b[0]), "r"(b[1]));
}

#define CP16(dst, src) \
    asm volatile("cp.async.cg.shared.global [%0], [%1], 16;" :: "r"(dst), "l"(src))
#define CP_COMMIT() asm volatile("cp.async.commit_group;")
#define CP_WAIT2()  asm volatile("cp.async.wait_group 2;")

__global__ void __launch_bounds__(256, 2)
gemm_fp16(const float* __restrict__ bias, float* __restrict__ out) {
    extern __shared__ char sm[];
    const uint32_t sb = smem_u32(sm);
    const int tid  = threadIdx.x;
    const int lane = tid & 31;
    const int wid  = tid >> 5;
    const int wm   = wid & 3;        // 4 m-groups of 32
    const int wn   = wid >> 2;       // 2 n-groups of 64
    const int m0   = blockIdx.y * 128;
    const int n0   = blockIdx.x * 128;

    // cp.async mapping: thread -> (rows tid/4 and +64, 16B chunk col = tid%4)
    const int crow = tid >> 2;
    const int ccol = tid & 3;
    const __half* gxh = g_xhi + (size_t)(m0 + crow) * DIN + ccol * 8;
    const __half* gwh = g_whi + (size_t)(n0 + crow) * DIN + ccol * 8;
    const uint32_t sts0 = swz64((uint32_t)crow * 64 + (uint32_t)ccol * 16);

    // unswizzled ldmatrix lane offsets; swizzle applied after adding ks
    const uint32_t a_off = (uint32_t)(wm * 32 + (lane & 15)) * 64 + (uint32_t)(lane >> 4) * 16;
    const uint32_t b_off = (uint32_t)(wn * 64 + (lane >> 4) * 8 + (lane & 7)) * 64 +
                           (uint32_t)((lane >> 3) & 1) * 16;

    float acc[2][8][4];
#pragma unroll
    for (int mt = 0; mt < 2; ++mt)
#pragma unroll
        for (int nt = 0; nt < 8; ++nt)
#pragma unroll
            for (int c = 0; c < 4; ++c) acc[mt][nt][c] = 0.f;

#define ISSUE(kt) do {                                                           \
        const uint32_t st_ = sb + ((kt) % STAGES) * STG;                         \
        const size_t go_ = (size_t)(kt) * BK;                                    \
        CP16(st_ + XHI_OFF + sts0,        gxh + go_);                            \
        CP16(st_ + XHI_OFF + sts0 + 4096, gxh + go_ + (size_t)64 * DIN);         \
        CP16(st_ + WHI_OFF + sts0,        gwh + go_);                            \
        CP16(st_ + WHI_OFF + sts0 + 4096, gwh + go_ + (size_t)64 * DIN);         \
    } while (0)

    ISSUE(0); CP_COMMIT();
    ISSUE(1); CP_COMMIT();
    ISSUE(2); CP_COMMIT();

    for (int kt = 0; kt < NKT; ++kt) {
        CP_WAIT2();
        __syncthreads();

        if (kt + 3 < NKT) { ISSUE(kt + 3); }
        CP_COMMIT();

        const uint32_t st = sb + (kt % STAGES) * STG;
#pragma unroll
        for (int s = 0; s < 2; ++s) {
            const uint32_t ks = s * 32;
            const uint32_t a_sw = swz64(a_off + ks);
            const uint32_t b_sw = swz64(b_off + ks);

            uint32_t bh[4][4];
#pragma unroll
            for (int j = 0; j < 4; ++j)
                ldsm4(bh[j], st + WHI_OFF + b_sw + j * 1024);

            uint32_t ah[2][4];
#pragma unroll
            for (int mt = 0; mt < 2; ++mt)
                ldsm4(ah[mt], st + XHI_OFF + a_sw + mt * 1024);

#pragma unroll
            for (int mt = 0; mt < 2; ++mt)
#pragma unroll
                for (int nt = 0; nt < 8; ++nt)
                    mma16816(acc[mt][nt], ah[mt], &bh[nt >> 1][(nt & 1) * 2]);
        }
    }

    // ---- epilogue: add bias, store fp32 (float2) ----
    const int erow = m0 + wm * 32 + (lane >> 2);
    const int ecol = n0 + wn * 64 + (lane & 3) * 2;
#pragma unroll
    for (int nt = 0; nt < 8; ++nt) {
        const int c = ecol + nt * 8;
        const float b0 = bias[c], b1 = bias[c + 1];
#pragma unroll
        for (int mt = 0; mt < 2; ++mt) {
            const int r = erow + mt * 16;
            float2 o0 = make_float2(acc[mt][nt][0] + b0, acc[mt][nt][1] + b1);
            float2 o1 = make_float2(acc[mt][nt][2] + b0, acc[mt][nt][3] + b1);
            *reinterpret_cast<float2*>(out + (size_t)r * DOUT + c)       = o0;
            *reinterpret_cast<float2*>(out + (size_t)(r + 8) * DOUT + c) = o1;
        }
    }
}

// ---------------- launch ----------------
extern "C" void kernel_launch(void* const* d_in, const int* in_sizes, int n_in,
                              void* d_out, int out_size) {
    const float* x  = (const float*)d_in[0];
    const float* W  = (const float*)d_in[1];
    const float* b  = (const float*)d_in[2];
    const float* A1 = (const float*)d_in[3];
    const float* B1 = (const float*)d_in[4];
    const float* A2 = (const float*)d_in[5];
    const float* B2 = (const float*)d_in[6];
    float* out = (float*)d_out;

    cudaFuncSetAttribute(gemm_fp16, cudaFuncAttributeMaxDynamicSharedMemorySize,
                         STAGES * STG);

    prep_kernel<<<XBLK + WBLK, 256>>>(x, W, A1, B1, A2, B2);

    dim3 grid(DOUT / 128, TOKENS / 128);   // (n-tiles=8, m-tiles=256)
    gemm_fp16<<<grid, 256, STAGES * STG>>>(b, out);
}